// round 1
// baseline (speedup 1.0000x reference)
#include <cuda_runtime.h>
#include <math.h>

// Problem constants
#define BSZ   2
#define TSEQ  2048
#define DMODEL 1024
#define NHEAD 16
#define HDIM  64
#define INNER 1024          // NHEAD*HDIM
#define E3    3072          // 3*INNER
#define MROWS (BSZ*TSEQ)    // 4096

// Scratch (static device globals: allocation-free per harness rules)
__device__ float g_Q[BSZ*NHEAD*TSEQ*HDIM];
__device__ float g_K[BSZ*NHEAD*TSEQ*HDIM];
__device__ float g_V[BSZ*NHEAD*TSEQ*HDIM];
__device__ float g_ATT[MROWS*INNER];

// ---------------------------------------------------------------------------
// GEMM 1: qkv[m,e] = sum_k x[m,k]*qkv_w[e,k] + qkv_b[e], scattered to Q/K/V
// 128x128 tile, BK=8, 256 threads, 8x8 fragment per thread.
// ---------------------------------------------------------------------------
__global__ __launch_bounds__(256) void gemm_qkv_kernel(
    const float* __restrict__ A, const float* __restrict__ W,
    const float* __restrict__ bias)
{
    const int K = DMODEL;
    __shared__ float As[8][128];
    __shared__ float Bs[8][128];
    const int n0 = blockIdx.x * 128;
    const int m0 = blockIdx.y * 128;
    const int tid = threadIdx.x;
    const int tx = tid & 15, ty = tid >> 4;
    const int lrow = tid >> 1;
    const int lq = (tid & 1) * 4;

    float acc[8][8];
#pragma unroll
    for (int i = 0; i < 8; i++)
#pragma unroll
        for (int j = 0; j < 8; j++) acc[i][j] = 0.f;

    const float* Aptr = A + (size_t)(m0 + lrow) * K + lq;
    const float* Wptr = W + (size_t)(n0 + lrow) * K + lq;

    for (int k0 = 0; k0 < K; k0 += 8) {
        float4 av = *reinterpret_cast<const float4*>(Aptr + k0);
        float4 wv = *reinterpret_cast<const float4*>(Wptr + k0);
        As[lq + 0][lrow] = av.x; As[lq + 1][lrow] = av.y;
        As[lq + 2][lrow] = av.z; As[lq + 3][lrow] = av.w;
        Bs[lq + 0][lrow] = wv.x; Bs[lq + 1][lrow] = wv.y;
        Bs[lq + 2][lrow] = wv.z; Bs[lq + 3][lrow] = wv.w;
        __syncthreads();
#pragma unroll
        for (int kk = 0; kk < 8; kk++) {
            float4 a0 = *reinterpret_cast<const float4*>(&As[kk][ty * 8]);
            float4 a1 = *reinterpret_cast<const float4*>(&As[kk][ty * 8 + 4]);
            float4 b0 = *reinterpret_cast<const float4*>(&Bs[kk][tx * 8]);
            float4 b1 = *reinterpret_cast<const float4*>(&Bs[kk][tx * 8 + 4]);
            float a[8] = {a0.x, a0.y, a0.z, a0.w, a1.x, a1.y, a1.z, a1.w};
            float b[8] = {b0.x, b0.y, b0.z, b0.w, b1.x, b1.y, b1.z, b1.w};
#pragma unroll
            for (int i = 0; i < 8; i++)
#pragma unroll
                for (int j = 0; j < 8; j++)
                    acc[i][j] = fmaf(a[i], b[j], acc[i][j]);
        }
        __syncthreads();
    }

    // Epilogue: scatter into g_Q / g_K / g_V with layout [b][h][t][d]
#pragma unroll
    for (int i = 0; i < 8; i++) {
        int mm = m0 + ty * 8 + i;
        int bb = mm >> 11;        // / TSEQ
        int tt = mm & (TSEQ - 1);
#pragma unroll
        for (int j4 = 0; j4 < 8; j4 += 4) {
            int e = n0 + tx * 8 + j4;
            float4 v;
            v.x = acc[i][j4 + 0] + bias[e + 0];
            v.y = acc[i][j4 + 1] + bias[e + 1];
            v.z = acc[i][j4 + 2] + bias[e + 2];
            v.w = acc[i][j4 + 3] + bias[e + 3];
            int which = e >> 10;          // /INNER
            int h = (e >> 6) & (NHEAD - 1);
            int d = e & (HDIM - 1);
            float* dst = (which == 0) ? g_Q : (which == 1) ? g_K : g_V;
            *reinterpret_cast<float4*>(
                &dst[((size_t)(bb * NHEAD + h) * TSEQ + tt) * HDIM + d]) = v;
        }
    }
}

// ---------------------------------------------------------------------------
// Flash attention with ANTI-causal mask (keep key j >= query i).
// 128-query x 64-key tiles; 256 threads; thread fragment: S 8x4, O 8x4.
// Mask value -1e30: fully-masked-tile rows produce garbage that the online
// rescale (alpha = exp(-1e30 - m_real) = 0) wipes exactly once real keys land.
// ---------------------------------------------------------------------------
#define ATT_SMEM ((128*65 + 64*65 + 64*65 + 128*65) * 4)

__global__ __launch_bounds__(256) void attn_kernel()
{
    extern __shared__ float sm[];
    float* Qs = sm;                 // [128][65]
    float* Ks = Qs + 128 * 65;      // [64][65]
    float* Vs = Ks + 64 * 65;       // [64][65]
    float* Ps = Vs + 64 * 65;       // [128][65]

    const int q0 = blockIdx.x * 128;
    const int h = blockIdx.y;
    const int b = blockIdx.z;
    const size_t head_off = (size_t)(b * NHEAD + h) * TSEQ * HDIM;
    const float* Qg = g_Q + head_off;
    const float* Kg = g_K + head_off;
    const float* Vg = g_V + head_off;

    const int tid = threadIdx.x;
    const int tx = tid & 15, ty = tid >> 4;

    // Load Q tile (128x64)
#pragma unroll
    for (int it = 0; it < 8; it++) {
        int idx = tid + it * 256;       // 0..2047 float4 slots
        int r = idx >> 4, c4 = (idx & 15) * 4;
        float4 v = *reinterpret_cast<const float4*>(&Qg[(size_t)(q0 + r) * HDIM + c4]);
        Qs[r * 65 + c4 + 0] = v.x; Qs[r * 65 + c4 + 1] = v.y;
        Qs[r * 65 + c4 + 2] = v.z; Qs[r * 65 + c4 + 3] = v.w;
    }

    float mrow[8], lrow[8], o[8][4];
#pragma unroll
    for (int i = 0; i < 8; i++) {
        mrow[i] = -1e30f; lrow[i] = 0.f;
#pragma unroll
        for (int j = 0; j < 4; j++) o[i][j] = 0.f;
    }
    __syncthreads();

    const float scale = 0.125f;   // 1/sqrt(64)

    for (int j0 = q0; j0 < TSEQ; j0 += 64) {
        // Load K/V tiles (64x64 each)
#pragma unroll
        for (int it = 0; it < 4; it++) {
            int idx = tid + it * 256;
            int r = idx >> 4, c4 = (idx & 15) * 4;
            float4 kv = *reinterpret_cast<const float4*>(&Kg[(size_t)(j0 + r) * HDIM + c4]);
            float4 vv = *reinterpret_cast<const float4*>(&Vg[(size_t)(j0 + r) * HDIM + c4]);
            Ks[r * 65 + c4 + 0] = kv.x; Ks[r * 65 + c4 + 1] = kv.y;
            Ks[r * 65 + c4 + 2] = kv.z; Ks[r * 65 + c4 + 3] = kv.w;
            Vs[r * 65 + c4 + 0] = vv.x; Vs[r * 65 + c4 + 1] = vv.y;
            Vs[r * 65 + c4 + 2] = vv.z; Vs[r * 65 + c4 + 3] = vv.w;
        }
        __syncthreads();

        // S = Q * K^T fragment
        float s[8][4];
#pragma unroll
        for (int i = 0; i < 8; i++)
#pragma unroll
            for (int j = 0; j < 4; j++) s[i][j] = 0.f;

        for (int d = 0; d < HDIM; d++) {
            float qv[8], kv[4];
#pragma unroll
            for (int i = 0; i < 8; i++) qv[i] = Qs[(ty * 8 + i) * 65 + d];
#pragma unroll
            for (int j = 0; j < 4; j++) kv[j] = Ks[(tx * 4 + j) * 65 + d];
#pragma unroll
            for (int i = 0; i < 8; i++)
#pragma unroll
                for (int j = 0; j < 4; j++)
                    s[i][j] = fmaf(qv[i], kv[j], s[i][j]);
        }

        const bool diag = (j0 < q0 + 128);

#pragma unroll
        for (int i = 0; i < 8; i++) {
            int qi = q0 + ty * 8 + i;
            float tmax = -1e30f;
#pragma unroll
            for (int j = 0; j < 4; j++) {
                float v = s[i][j] * scale;
                if (diag && (j0 + tx * 4 + j) < qi) v = -1e30f;  // keep j >= i
                s[i][j] = v;
                tmax = fmaxf(tmax, v);
            }
#pragma unroll
            for (int off = 8; off > 0; off >>= 1)
                tmax = fmaxf(tmax, __shfl_xor_sync(0xffffffffu, tmax, off));
            float mnew = fmaxf(mrow[i], tmax);
            float alpha = __expf(mrow[i] - mnew);
            mrow[i] = mnew;
            float rsum = 0.f;
#pragma unroll
            for (int j = 0; j < 4; j++) {
                float p = __expf(s[i][j] - mnew);
                s[i][j] = p;
                rsum += p;
            }
#pragma unroll
            for (int off = 8; off > 0; off >>= 1)
                rsum += __shfl_xor_sync(0xffffffffu, rsum, off);
            lrow[i] = lrow[i] * alpha + rsum;
#pragma unroll
            for (int j = 0; j < 4; j++) o[i][j] *= alpha;
#pragma unroll
            for (int j = 0; j < 4; j++)
                Ps[(ty * 8 + i) * 65 + tx * 4 + j] = s[i][j];
        }
        __syncthreads();

        // O += P * V
        for (int jj = 0; jj < 64; jj++) {
            float pv[8], vv[4];
#pragma unroll
            for (int i = 0; i < 8; i++) pv[i] = Ps[(ty * 8 + i) * 65 + jj];
#pragma unroll
            for (int j = 0; j < 4; j++) vv[j] = Vs[jj * 65 + tx * 4 + j];
#pragma unroll
            for (int i = 0; i < 8; i++)
#pragma unroll
                for (int j = 0; j < 4; j++)
                    o[i][j] = fmaf(pv[i], vv[j], o[i][j]);
        }
        __syncthreads();
    }

    // Normalize and write [B,T,INNER]
#pragma unroll
    for (int i = 0; i < 8; i++) {
        int t = q0 + ty * 8 + i;
        float inv = 1.0f / lrow[i];
        float4 v;
        v.x = o[i][0] * inv; v.y = o[i][1] * inv;
        v.z = o[i][2] * inv; v.w = o[i][3] * inv;
        *reinterpret_cast<float4*>(
            &g_ATT[((size_t)b * TSEQ + t) * INNER + h * HDIM + tx * 4]) = v;
    }
}

// ---------------------------------------------------------------------------
// GEMM 2: out[m,n] = sum_k g_ATT[m,k]*out_w[n,k] + out_b[n]
// ---------------------------------------------------------------------------
__global__ __launch_bounds__(256) void gemm_out_kernel(
    const float* __restrict__ W, const float* __restrict__ bias,
    float* __restrict__ C)
{
    const int K = INNER;
    __shared__ float As[8][128];
    __shared__ float Bs[8][128];
    const int n0 = blockIdx.x * 128;
    const int m0 = blockIdx.y * 128;
    const int tid = threadIdx.x;
    const int tx = tid & 15, ty = tid >> 4;
    const int lrow = tid >> 1;
    const int lq = (tid & 1) * 4;

    float acc[8][8];
#pragma unroll
    for (int i = 0; i < 8; i++)
#pragma unroll
        for (int j = 0; j < 8; j++) acc[i][j] = 0.f;

    const float* Aptr = g_ATT + (size_t)(m0 + lrow) * K + lq;
    const float* Wptr = W + (size_t)(n0 + lrow) * K + lq;

    for (int k0 = 0; k0 < K; k0 += 8) {
        float4 av = *reinterpret_cast<const float4*>(Aptr + k0);
        float4 wv = *reinterpret_cast<const float4*>(Wptr + k0);
        As[lq + 0][lrow] = av.x; As[lq + 1][lrow] = av.y;
        As[lq + 2][lrow] = av.z; As[lq + 3][lrow] = av.w;
        Bs[lq + 0][lrow] = wv.x; Bs[lq + 1][lrow] = wv.y;
        Bs[lq + 2][lrow] = wv.z; Bs[lq + 3][lrow] = wv.w;
        __syncthreads();
#pragma unroll
        for (int kk = 0; kk < 8; kk++) {
            float4 a0 = *reinterpret_cast<const float4*>(&As[kk][ty * 8]);
            float4 a1 = *reinterpret_cast<const float4*>(&As[kk][ty * 8 + 4]);
            float4 b0 = *reinterpret_cast<const float4*>(&Bs[kk][tx * 8]);
            float4 b1 = *reinterpret_cast<const float4*>(&Bs[kk][tx * 8 + 4]);
            float a[8] = {a0.x, a0.y, a0.z, a0.w, a1.x, a1.y, a1.z, a1.w};
            float b[8] = {b0.x, b0.y, b0.z, b0.w, b1.x, b1.y, b1.z, b1.w};
#pragma unroll
            for (int i = 0; i < 8; i++)
#pragma unroll
                for (int j = 0; j < 8; j++)
                    acc[i][j] = fmaf(a[i], b[j], acc[i][j]);
        }
        __syncthreads();
    }

#pragma unroll
    for (int i = 0; i < 8; i++) {
        int mm = m0 + ty * 8 + i;
#pragma unroll
        for (int j4 = 0; j4 < 8; j4 += 4) {
            int n = n0 + tx * 8 + j4;
            float4 v;
            v.x = acc[i][j4 + 0] + bias[n + 0];
            v.y = acc[i][j4 + 1] + bias[n + 1];
            v.z = acc[i][j4 + 2] + bias[n + 2];
            v.w = acc[i][j4 + 3] + bias[n + 3];
            *reinterpret_cast<float4*>(&C[(size_t)mm * DMODEL + n]) = v;
        }
    }
}

// ---------------------------------------------------------------------------
extern "C" void kernel_launch(void* const* d_in, const int* in_sizes, int n_in,
                              void* d_out, int out_size)
{
    const float* x     = (const float*)d_in[0];
    const float* qkv_w = (const float*)d_in[1];
    const float* qkv_b = (const float*)d_in[2];
    const float* out_w = (const float*)d_in[3];
    const float* out_b = (const float*)d_in[4];
    float* out = (float*)d_out;

    cudaFuncSetAttribute(attn_kernel,
                         cudaFuncAttributeMaxDynamicSharedMemorySize, ATT_SMEM);

    dim3 g1(E3 / 128, MROWS / 128);
    gemm_qkv_kernel<<<g1, 256>>>(x, qkv_w, qkv_b);

    dim3 g2(TSEQ / 128, NHEAD, BSZ);
    attn_kernel<<<g2, 256, ATT_SMEM>>>();

    dim3 g3(INNER / 128, MROWS / 128);
    gemm_out_kernel<<<g3, 256>>>(out_w, out_b, out);
}

// round 3
// speedup vs baseline: 1.5111x; 1.5111x over previous
#include <cuda_runtime.h>
#include <cuda_bf16.h>
#include <cstdint>
#include <math.h>

// Problem constants
#define BSZ   2
#define TSEQ  2048
#define DMODEL 1024
#define NHEAD 16
#define HDIM  64
#define INNER 1024
#define E3    3072
#define MROWS (BSZ*TSEQ)    // 4096
#define KDIM  1024          // both GEMMs have K=1024

// Scratch
__device__ float g_Q[(size_t)BSZ*NHEAD*TSEQ*HDIM];
__device__ float g_K[(size_t)BSZ*NHEAD*TSEQ*HDIM];
__device__ float g_V[(size_t)BSZ*NHEAD*TSEQ*HDIM];
__device__ float g_ATT[(size_t)MROWS*INNER];

// ===========================================================================
// mma.sync helpers (arch-portable tensor core path; tcgen05 unavailable:
// harness compiles via compute_103 virtual target, no sm_103a features)
// ===========================================================================
__device__ __forceinline__ uint32_t smem_u32(const void* p) {
    uint32_t a;
    asm("{ .reg .u64 t; cvta.to.shared.u64 t, %1; cvt.u32.u64 %0, t; }"
        : "=r"(a) : "l"(p));
    return a;
}
__device__ __forceinline__ void ldsm_x4(uint32_t& r0, uint32_t& r1,
                                        uint32_t& r2, uint32_t& r3, uint32_t a) {
    asm volatile("ldmatrix.sync.aligned.m8n8.x4.shared.b16 {%0,%1,%2,%3}, [%4];"
                 : "=r"(r0), "=r"(r1), "=r"(r2), "=r"(r3) : "r"(a));
}
__device__ __forceinline__ void mma_bf16(float* d, const uint32_t* a,
                                         uint32_t b0, uint32_t b1) {
    asm volatile(
        "mma.sync.aligned.m16n8k16.row.col.f32.bf16.bf16.f32 "
        "{%0,%1,%2,%3}, {%4,%5,%6,%7}, {%8,%9}, {%0,%1,%2,%3};"
        : "+f"(d[0]), "+f"(d[1]), "+f"(d[2]), "+f"(d[3])
        : "r"(a[0]), "r"(a[1]), "r"(a[2]), "r"(a[3]), "r"(b0), "r"(b1));
}

// ===========================================================================
// Split-bf16 tensor-core GEMM: C[m,n] = sum_k A[m,k]*B[n,k] + bias[n]
// CTA tile 128x128, warp tile 32x64 (4x2 warps), K-chunk 32, double buffered.
// A = Ah + Al (bf16 split), C accumulates Ah*Bh + Ah*Bl + Al*Bh in fp32.
// mode 0: A = x, scatter output into g_Q/g_K/g_V ([b][h][t][d])
// mode 1: A = g_ATT, write C[m*1024 + n]
// ===========================================================================
#define GK_CH 32            // K elems per chunk
#define NCH   (KDIM/GK_CH)  // 32 chunks
#define LDK   40            // bf16 elems per smem row (80B stride, conflict-free)
#define TILE_ELEMS (128*LDK)
// smem: A[buf][part] then B[buf][part]; part 0=hi, 1=lo
#define OFF_A(buf,part) ((uint32_t)(((buf)*2+(part))*TILE_ELEMS)*2u)
#define OFF_B(buf,part) ((uint32_t)((4+(buf)*2+(part))*TILE_ELEMS)*2u)
#define GEMM_SMEM (8*TILE_ELEMS*2)   // 81920 B

__device__ __forceinline__ void cvt_split(float4 v, uint2& hi, uint2& lo) {
    __nv_bfloat162 h01 = __floats2bfloat162_rn(v.x, v.y);
    __nv_bfloat162 h23 = __floats2bfloat162_rn(v.z, v.w);
    __nv_bfloat162 l01 = __floats2bfloat162_rn(v.x - __bfloat162float(h01.x),
                                               v.y - __bfloat162float(h01.y));
    __nv_bfloat162 l23 = __floats2bfloat162_rn(v.z - __bfloat162float(h23.x),
                                               v.w - __bfloat162float(h23.y));
    hi.x = *reinterpret_cast<uint32_t*>(&h01);
    hi.y = *reinterpret_cast<uint32_t*>(&h23);
    lo.x = *reinterpret_cast<uint32_t*>(&l01);
    lo.y = *reinterpret_cast<uint32_t*>(&l23);
}

__global__ __launch_bounds__(256) void gemm_mma_kernel(
    const float* __restrict__ A, const float* __restrict__ B,
    const float* __restrict__ bias, float* __restrict__ C, int mode)
{
    extern __shared__ char smem[];
    const uint32_t sb = smem_u32(smem);
    const int tid  = threadIdx.x;
    const int lane = tid & 31;
    const int warp = tid >> 5;
    const int wm = warp & 3;          // 0..3 -> m offset 32*wm
    const int wn = warp >> 2;         // 0..1 -> n offset 64*wn
    const int n0 = blockIdx.x * 128;
    const int m0 = blockIdx.y * 128;

    const float* Asrc = (mode == 0) ? A : g_ATT;

    // per-thread global load coords: 1024 float4 slots per 128x32 tile
    const int gr  = tid >> 1;             // row 0..127   (2 slots per row? no)
    // lin = tid + it*256, it 0..3 ; r = lin>>3 (0..127), c4 = (lin&7)*4
    float4 pa[4], pb[4];

    // ---- load chunk helpers (macro-ish via lambdas) ----
    auto load_regs = [&](int kc) {
#pragma unroll
        for (int it = 0; it < 4; it++) {
            int lin = tid + it * 256;
            int r = lin >> 3, c4 = (lin & 7) * 4;
            pa[it] = *reinterpret_cast<const float4*>(
                Asrc + (size_t)(m0 + r) * KDIM + kc + c4);
            pb[it] = *reinterpret_cast<const float4*>(
                B + (size_t)(n0 + r) * KDIM + kc + c4);
        }
    };
    auto store_regs = [&](int buf) {
#pragma unroll
        for (int it = 0; it < 4; it++) {
            int lin = tid + it * 256;
            int r = lin >> 3, c4 = (lin & 7) * 4;
            uint32_t eoff = (uint32_t)(r * LDK + c4) * 2u;
            uint2 hi, lo;
            cvt_split(pa[it], hi, lo);
            *reinterpret_cast<uint2*>(smem + OFF_A(buf, 0) + eoff) = hi;
            *reinterpret_cast<uint2*>(smem + OFF_A(buf, 1) + eoff) = lo;
            cvt_split(pb[it], hi, lo);
            *reinterpret_cast<uint2*>(smem + OFF_B(buf, 0) + eoff) = hi;
            *reinterpret_cast<uint2*>(smem + OFF_B(buf, 1) + eoff) = lo;
        }
    };

    float acc[2][8][4];
#pragma unroll
    for (int i = 0; i < 2; i++)
#pragma unroll
        for (int j = 0; j < 8; j++)
#pragma unroll
            for (int q = 0; q < 4; q++) acc[i][j][q] = 0.f;

    // ldmatrix address components
    const int aRow = wm * 32 + (lane & 15);
    const int aCol = (lane >> 4) * 8;                 // + ks
    const int bRow = wn * 64 + ((lane >> 4) * 8) + (lane & 7);
    const int bCol = ((lane >> 3) & 1) * 8;           // + ks
    // (bq = lane>>3: 0,1 -> n-rows 0-7 k/k+8 ; 2,3 -> n-rows 8-15 k/k+8)

    load_regs(0);
    store_regs(0);
    __syncthreads();

    for (int c = 0; c < NCH; c++) {
        const int buf = c & 1;
        if (c + 1 < NCH) load_regs((c + 1) * GK_CH);

        const uint32_t baseAH = sb + OFF_A(buf, 0);
        const uint32_t baseAL = sb + OFF_A(buf, 1);
        const uint32_t baseBH = sb + OFF_B(buf, 0);
        const uint32_t baseBL = sb + OFF_B(buf, 1);

#pragma unroll
        for (int ks = 0; ks < GK_CH; ks += 16) {
            uint32_t ah[2][4], bh[4][4], bl[4][4];
#pragma unroll
            for (int i = 0; i < 2; i++) {
                uint32_t addr = baseAH +
                    (uint32_t)((aRow + i * 16) * LDK + ks + aCol) * 2u;
                ldsm_x4(ah[i][0], ah[i][1], ah[i][2], ah[i][3], addr);
            }
#pragma unroll
            for (int j2 = 0; j2 < 4; j2++) {
                uint32_t addr = baseBH +
                    (uint32_t)((bRow + j2 * 16) * LDK + ks + bCol) * 2u;
                ldsm_x4(bh[j2][0], bh[j2][1], bh[j2][2], bh[j2][3], addr);
            }
#pragma unroll
            for (int j2 = 0; j2 < 4; j2++) {
                uint32_t addr = baseBL +
                    (uint32_t)((bRow + j2 * 16) * LDK + ks + bCol) * 2u;
                ldsm_x4(bl[j2][0], bl[j2][1], bl[j2][2], bl[j2][3], addr);
            }
            // Ah*Bh and Ah*Bl
#pragma unroll
            for (int i = 0; i < 2; i++)
#pragma unroll
                for (int j2 = 0; j2 < 4; j2++) {
                    mma_bf16(acc[i][j2 * 2 + 0], ah[i], bh[j2][0], bh[j2][1]);
                    mma_bf16(acc[i][j2 * 2 + 1], ah[i], bh[j2][2], bh[j2][3]);
                    mma_bf16(acc[i][j2 * 2 + 0], ah[i], bl[j2][0], bl[j2][1]);
                    mma_bf16(acc[i][j2 * 2 + 1], ah[i], bl[j2][2], bl[j2][3]);
                }
            // Al*Bh (reuse ah regs)
#pragma unroll
            for (int i = 0; i < 2; i++) {
                uint32_t addr = baseAL +
                    (uint32_t)((aRow + i * 16) * LDK + ks + aCol) * 2u;
                ldsm_x4(ah[i][0], ah[i][1], ah[i][2], ah[i][3], addr);
            }
#pragma unroll
            for (int i = 0; i < 2; i++)
#pragma unroll
                for (int j2 = 0; j2 < 4; j2++) {
                    mma_bf16(acc[i][j2 * 2 + 0], ah[i], bh[j2][0], bh[j2][1]);
                    mma_bf16(acc[i][j2 * 2 + 1], ah[i], bh[j2][2], bh[j2][3]);
                }
        }

        if (c + 1 < NCH) store_regs(buf ^ 1);
        __syncthreads();
    }

    // Epilogue
#pragma unroll
    for (int i = 0; i < 2; i++) {
#pragma unroll
        for (int j = 0; j < 8; j++) {
            int row = m0 + wm * 32 + i * 16 + (lane >> 2);
            int col = n0 + wn * 64 + j * 8 + (lane & 3) * 2;
            float2 v0, v1;
            v0.x = acc[i][j][0] + bias[col];
            v0.y = acc[i][j][1] + bias[col + 1];
            v1.x = acc[i][j][2] + bias[col];
            v1.y = acc[i][j][3] + bias[col + 1];
            if (mode == 0) {
                int bb = row >> 11, tt = row & (TSEQ - 1);
                int which = col >> 10, h = (col >> 6) & (NHEAD - 1), d = col & (HDIM - 1);
                float* dst = (which == 0) ? g_Q : (which == 1) ? g_K : g_V;
                size_t base = ((size_t)(bb * NHEAD + h) * TSEQ);
                *reinterpret_cast<float2*>(&dst[(base + tt) * HDIM + d]) = v0;
                *reinterpret_cast<float2*>(&dst[(base + tt + 8) * HDIM + d]) = v1;
            } else {
                *reinterpret_cast<float2*>(&C[(size_t)row * DMODEL + col]) = v0;
                *reinterpret_cast<float2*>(&C[(size_t)(row + 8) * DMODEL + col]) = v1;
            }
        }
    }
}

// ===========================================================================
// Flash attention (fp32 SIMT), anti-causal mask (keep key j >= query i).
// Unchanged from round 1 (passed, rel_err 7.7e-7).
// ===========================================================================
#define ATT_SMEM ((128*65 + 64*65 + 64*65 + 128*65) * 4)

__global__ __launch_bounds__(256) void attn_kernel()
{
    extern __shared__ float sm[];
    float* Qs = sm;
    float* Ks = Qs + 128 * 65;
    float* Vs = Ks + 64 * 65;
    float* Ps = Vs + 64 * 65;

    const int q0 = blockIdx.x * 128;
    const int h = blockIdx.y;
    const int b = blockIdx.z;
    const size_t head_off = (size_t)(b * NHEAD + h) * TSEQ * HDIM;
    const float* Qg = g_Q + head_off;
    const float* Kg = g_K + head_off;
    const float* Vg = g_V + head_off;

    const int tid = threadIdx.x;
    const int tx = tid & 15, ty = tid >> 4;

#pragma unroll
    for (int it = 0; it < 8; it++) {
        int idx = tid + it * 256;
        int r = idx >> 4, c4 = (idx & 15) * 4;
        float4 v = *reinterpret_cast<const float4*>(&Qg[(size_t)(q0 + r) * HDIM + c4]);
        Qs[r * 65 + c4 + 0] = v.x; Qs[r * 65 + c4 + 1] = v.y;
        Qs[r * 65 + c4 + 2] = v.z; Qs[r * 65 + c4 + 3] = v.w;
    }

    float mrow[8], lrow[8], o[8][4];
#pragma unroll
    for (int i = 0; i < 8; i++) {
        mrow[i] = -1e30f; lrow[i] = 0.f;
#pragma unroll
        for (int j = 0; j < 4; j++) o[i][j] = 0.f;
    }
    __syncthreads();

    const float scale = 0.125f;

    for (int j0 = q0; j0 < TSEQ; j0 += 64) {
#pragma unroll
        for (int it = 0; it < 4; it++) {
            int idx = tid + it * 256;
            int r = idx >> 4, c4 = (idx & 15) * 4;
            float4 kv = *reinterpret_cast<const float4*>(&Kg[(size_t)(j0 + r) * HDIM + c4]);
            float4 vv = *reinterpret_cast<const float4*>(&Vg[(size_t)(j0 + r) * HDIM + c4]);
            Ks[r * 65 + c4 + 0] = kv.x; Ks[r * 65 + c4 + 1] = kv.y;
            Ks[r * 65 + c4 + 2] = kv.z; Ks[r * 65 + c4 + 3] = kv.w;
            Vs[r * 65 + c4 + 0] = vv.x; Vs[r * 65 + c4 + 1] = vv.y;
            Vs[r * 65 + c4 + 2] = vv.z; Vs[r * 65 + c4 + 3] = vv.w;
        }
        __syncthreads();

        float s[8][4];
#pragma unroll
        for (int i = 0; i < 8; i++)
#pragma unroll
            for (int j = 0; j < 4; j++) s[i][j] = 0.f;

        for (int d = 0; d < HDIM; d++) {
            float qv[8], kv[4];
#pragma unroll
            for (int i = 0; i < 8; i++) qv[i] = Qs[(ty * 8 + i) * 65 + d];
#pragma unroll
            for (int j = 0; j < 4; j++) kv[j] = Ks[(tx * 4 + j) * 65 + d];
#pragma unroll
            for (int i = 0; i < 8; i++)
#pragma unroll
                for (int j = 0; j < 4; j++)
                    s[i][j] = fmaf(qv[i], kv[j], s[i][j]);
        }

        const bool diag = (j0 < q0 + 128);

#pragma unroll
        for (int i = 0; i < 8; i++) {
            int qi = q0 + ty * 8 + i;
            float tmax = -1e30f;
#pragma unroll
            for (int j = 0; j < 4; j++) {
                float v = s[i][j] * scale;
                if (diag && (j0 + tx * 4 + j) < qi) v = -1e30f;
                s[i][j] = v;
                tmax = fmaxf(tmax, v);
            }
#pragma unroll
            for (int off = 8; off > 0; off >>= 1)
                tmax = fmaxf(tmax, __shfl_xor_sync(0xffffffffu, tmax, off));
            float mnew = fmaxf(mrow[i], tmax);
            float alpha = __expf(mrow[i] - mnew);
            mrow[i] = mnew;
            float rsum = 0.f;
#pragma unroll
            for (int j = 0; j < 4; j++) {
                float p = __expf(s[i][j] - mnew);
                s[i][j] = p;
                rsum += p;
            }
#pragma unroll
            for (int off = 8; off > 0; off >>= 1)
                rsum += __shfl_xor_sync(0xffffffffu, rsum, off);
            lrow[i] = lrow[i] * alpha + rsum;
#pragma unroll
            for (int j = 0; j < 4; j++) o[i][j] *= alpha;
#pragma unroll
            for (int j = 0; j < 4; j++)
                Ps[(ty * 8 + i) * 65 + tx * 4 + j] = s[i][j];
        }
        __syncthreads();

        for (int jj = 0; jj < 64; jj++) {
            float pv[8], vv[4];
#pragma unroll
            for (int i = 0; i < 8; i++) pv[i] = Ps[(ty * 8 + i) * 65 + jj];
#pragma unroll
            for (int j = 0; j < 4; j++) vv[j] = Vs[jj * 65 + tx * 4 + j];
#pragma unroll
            for (int i = 0; i < 8; i++)
#pragma unroll
                for (int j = 0; j < 4; j++)
                    o[i][j] = fmaf(pv[i], vv[j], o[i][j]);
        }
        __syncthreads();
    }

#pragma unroll
    for (int i = 0; i < 8; i++) {
        int t = q0 + ty * 8 + i;
        float inv = 1.0f / lrow[i];
        float4 v;
        v.x = o[i][0] * inv; v.y = o[i][1] * inv;
        v.z = o[i][2] * inv; v.w = o[i][3] * inv;
        *reinterpret_cast<float4*>(
            &g_ATT[((size_t)b * TSEQ + t) * INNER + h * HDIM + tx * 4]) = v;
    }
}

// ===========================================================================
extern "C" void kernel_launch(void* const* d_in, const int* in_sizes, int n_in,
                              void* d_out, int out_size)
{
    const float* x     = (const float*)d_in[0];
    const float* qkv_w = (const float*)d_in[1];
    const float* qkv_b = (const float*)d_in[2];
    const float* out_w = (const float*)d_in[3];
    const float* out_b = (const float*)d_in[4];
    float* out = (float*)d_out;

    static int configured = 0;
    if (!configured) {
        cudaFuncSetAttribute(gemm_mma_kernel,
                             cudaFuncAttributeMaxDynamicSharedMemorySize, GEMM_SMEM);
        cudaFuncSetAttribute(attn_kernel,
                             cudaFuncAttributeMaxDynamicSharedMemorySize, ATT_SMEM);
        configured = 1;
    }

    // GEMM 1: qkv = x @ qkv_w^T + qkv_b, scattered into g_Q/g_K/g_V
    dim3 g1(E3 / 128, MROWS / 128);
    gemm_mma_kernel<<<g1, 256, GEMM_SMEM>>>(x, qkv_w, qkv_b, nullptr, 0);

    // Attention
    dim3 g2(TSEQ / 128, NHEAD, BSZ);
    attn_kernel<<<g2, 256, ATT_SMEM>>>();

    // GEMM 2: out = attn_out @ out_w^T + out_b
    dim3 g3(INNER / 128, MROWS / 128);
    gemm_mma_kernel<<<g3, 256, GEMM_SMEM>>>(nullptr, out_w, out_b, out, 1);
}

// round 4
// speedup vs baseline: 3.0182x; 1.9974x over previous
#include <cuda_runtime.h>
#include <cuda_bf16.h>
#include <cstdint>
#include <math.h>

// Problem constants
#define BSZ   2
#define TSEQ  2048
#define DMODEL 1024
#define NHEAD 16
#define HDIM  64
#define INNER 1024
#define E3    3072
#define MROWS (BSZ*TSEQ)    // 4096
#define KDIM  1024

// Scratch
__device__ float g_Q[(size_t)BSZ*NHEAD*TSEQ*HDIM];
__device__ float g_K[(size_t)BSZ*NHEAD*TSEQ*HDIM];
__device__ float g_V[(size_t)BSZ*NHEAD*TSEQ*HDIM];
__device__ float g_ATT[(size_t)MROWS*INNER];

// ===========================================================================
// mma.sync helpers
// ===========================================================================
__device__ __forceinline__ uint32_t smem_u32(const void* p) {
    uint32_t a;
    asm("{ .reg .u64 t; cvta.to.shared.u64 t, %1; cvt.u32.u64 %0, t; }"
        : "=r"(a) : "l"(p));
    return a;
}
__device__ __forceinline__ void ldsm_x4(uint32_t& r0, uint32_t& r1,
                                        uint32_t& r2, uint32_t& r3, uint32_t a) {
    asm volatile("ldmatrix.sync.aligned.m8n8.x4.shared.b16 {%0,%1,%2,%3}, [%4];"
                 : "=r"(r0), "=r"(r1), "=r"(r2), "=r"(r3) : "r"(a));
}
__device__ __forceinline__ void ldsm_x4_t(uint32_t& r0, uint32_t& r1,
                                          uint32_t& r2, uint32_t& r3, uint32_t a) {
    asm volatile("ldmatrix.sync.aligned.m8n8.x4.trans.shared.b16 {%0,%1,%2,%3}, [%4];"
                 : "=r"(r0), "=r"(r1), "=r"(r2), "=r"(r3) : "r"(a));
}
__device__ __forceinline__ void mma_bf16(float* d, const uint32_t* a,
                                         uint32_t b0, uint32_t b1) {
    asm volatile(
        "mma.sync.aligned.m16n8k16.row.col.f32.bf16.bf16.f32 "
        "{%0,%1,%2,%3}, {%4,%5,%6,%7}, {%8,%9}, {%0,%1,%2,%3};"
        : "+f"(d[0]), "+f"(d[1]), "+f"(d[2]), "+f"(d[3])
        : "r"(a[0]), "r"(a[1]), "r"(a[2]), "r"(a[3]), "r"(b0), "r"(b1));
}
__device__ __forceinline__ float ex2f(float x) {
    float r;
    asm("ex2.approx.f32 %0, %1;" : "=f"(r) : "f"(x));
    return r;
}
__device__ __forceinline__ uint32_t pack_bf16_hi(float a, float b) {
    __nv_bfloat162 h = __floats2bfloat162_rn(a, b);
    return *reinterpret_cast<uint32_t*>(&h);
}

// ===========================================================================
// Split-bf16 tensor-core GEMM (unchanged from round 3, passed)
// ===========================================================================
#define GK_CH 32
#define NCH   (KDIM/GK_CH)
#define LDK   40
#define TILE_ELEMS (128*LDK)
#define OFF_A(buf,part) ((uint32_t)(((buf)*2+(part))*TILE_ELEMS)*2u)
#define OFF_B(buf,part) ((uint32_t)((4+(buf)*2+(part))*TILE_ELEMS)*2u)
#define GEMM_SMEM (8*TILE_ELEMS*2)

__device__ __forceinline__ void cvt_split(float4 v, uint2& hi, uint2& lo) {
    __nv_bfloat162 h01 = __floats2bfloat162_rn(v.x, v.y);
    __nv_bfloat162 h23 = __floats2bfloat162_rn(v.z, v.w);
    __nv_bfloat162 l01 = __floats2bfloat162_rn(v.x - __bfloat162float(h01.x),
                                               v.y - __bfloat162float(h01.y));
    __nv_bfloat162 l23 = __floats2bfloat162_rn(v.z - __bfloat162float(h23.x),
                                               v.w - __bfloat162float(h23.y));
    hi.x = *reinterpret_cast<uint32_t*>(&h01);
    hi.y = *reinterpret_cast<uint32_t*>(&h23);
    lo.x = *reinterpret_cast<uint32_t*>(&l01);
    lo.y = *reinterpret_cast<uint32_t*>(&l23);
}

__global__ __launch_bounds__(256) void gemm_mma_kernel(
    const float* __restrict__ A, const float* __restrict__ B,
    const float* __restrict__ bias, float* __restrict__ C, int mode)
{
    extern __shared__ char smem[];
    const uint32_t sb = smem_u32(smem);
    const int tid  = threadIdx.x;
    const int lane = tid & 31;
    const int warp = tid >> 5;
    const int wm = warp & 3;
    const int wn = warp >> 2;
    const int n0 = blockIdx.x * 128;
    const int m0 = blockIdx.y * 128;

    const float* Asrc = (mode == 0) ? A : g_ATT;
    float4 pa[4], pb[4];

    auto load_regs = [&](int kc) {
#pragma unroll
        for (int it = 0; it < 4; it++) {
            int lin = tid + it * 256;
            int r = lin >> 3, c4 = (lin & 7) * 4;
            pa[it] = *reinterpret_cast<const float4*>(
                Asrc + (size_t)(m0 + r) * KDIM + kc + c4);
            pb[it] = *reinterpret_cast<const float4*>(
                B + (size_t)(n0 + r) * KDIM + kc + c4);
        }
    };
    auto store_regs = [&](int buf) {
#pragma unroll
        for (int it = 0; it < 4; it++) {
            int lin = tid + it * 256;
            int r = lin >> 3, c4 = (lin & 7) * 4;
            uint32_t eoff = (uint32_t)(r * LDK + c4) * 2u;
            uint2 hi, lo;
            cvt_split(pa[it], hi, lo);
            *reinterpret_cast<uint2*>(smem + OFF_A(buf, 0) + eoff) = hi;
            *reinterpret_cast<uint2*>(smem + OFF_A(buf, 1) + eoff) = lo;
            cvt_split(pb[it], hi, lo);
            *reinterpret_cast<uint2*>(smem + OFF_B(buf, 0) + eoff) = hi;
            *reinterpret_cast<uint2*>(smem + OFF_B(buf, 1) + eoff) = lo;
        }
    };

    float acc[2][8][4];
#pragma unroll
    for (int i = 0; i < 2; i++)
#pragma unroll
        for (int j = 0; j < 8; j++)
#pragma unroll
            for (int q = 0; q < 4; q++) acc[i][j][q] = 0.f;

    const int aRow = wm * 32 + (lane & 15);
    const int aCol = (lane >> 4) * 8;
    const int bRow = wn * 64 + ((lane >> 4) * 8) + (lane & 7);
    const int bCol = ((lane >> 3) & 1) * 8;

    load_regs(0);
    store_regs(0);
    __syncthreads();

    for (int c = 0; c < NCH; c++) {
        const int buf = c & 1;
        if (c + 1 < NCH) load_regs((c + 1) * GK_CH);

        const uint32_t baseAH = sb + OFF_A(buf, 0);
        const uint32_t baseAL = sb + OFF_A(buf, 1);
        const uint32_t baseBH = sb + OFF_B(buf, 0);
        const uint32_t baseBL = sb + OFF_B(buf, 1);

#pragma unroll
        for (int ks = 0; ks < GK_CH; ks += 16) {
            uint32_t ah[2][4], bh[4][4], bl[4][4];
#pragma unroll
            for (int i = 0; i < 2; i++) {
                uint32_t addr = baseAH +
                    (uint32_t)((aRow + i * 16) * LDK + ks + aCol) * 2u;
                ldsm_x4(ah[i][0], ah[i][1], ah[i][2], ah[i][3], addr);
            }
#pragma unroll
            for (int j2 = 0; j2 < 4; j2++) {
                uint32_t addr = baseBH +
                    (uint32_t)((bRow + j2 * 16) * LDK + ks + bCol) * 2u;
                ldsm_x4(bh[j2][0], bh[j2][1], bh[j2][2], bh[j2][3], addr);
            }
#pragma unroll
            for (int j2 = 0; j2 < 4; j2++) {
                uint32_t addr = baseBL +
                    (uint32_t)((bRow + j2 * 16) * LDK + ks + bCol) * 2u;
                ldsm_x4(bl[j2][0], bl[j2][1], bl[j2][2], bl[j2][3], addr);
            }
#pragma unroll
            for (int i = 0; i < 2; i++)
#pragma unroll
                for (int j2 = 0; j2 < 4; j2++) {
                    mma_bf16(acc[i][j2 * 2 + 0], ah[i], bh[j2][0], bh[j2][1]);
                    mma_bf16(acc[i][j2 * 2 + 1], ah[i], bh[j2][2], bh[j2][3]);
                    mma_bf16(acc[i][j2 * 2 + 0], ah[i], bl[j2][0], bl[j2][1]);
                    mma_bf16(acc[i][j2 * 2 + 1], ah[i], bl[j2][2], bl[j2][3]);
                }
#pragma unroll
            for (int i = 0; i < 2; i++) {
                uint32_t addr = baseAL +
                    (uint32_t)((aRow + i * 16) * LDK + ks + aCol) * 2u;
                ldsm_x4(ah[i][0], ah[i][1], ah[i][2], ah[i][3], addr);
            }
#pragma unroll
            for (int i = 0; i < 2; i++)
#pragma unroll
                for (int j2 = 0; j2 < 4; j2++) {
                    mma_bf16(acc[i][j2 * 2 + 0], ah[i], bh[j2][0], bh[j2][1]);
                    mma_bf16(acc[i][j2 * 2 + 1], ah[i], bh[j2][2], bh[j2][3]);
                }
        }

        if (c + 1 < NCH) store_regs(buf ^ 1);
        __syncthreads();
    }

#pragma unroll
    for (int i = 0; i < 2; i++) {
#pragma unroll
        for (int j = 0; j < 8; j++) {
            int row = m0 + wm * 32 + i * 16 + (lane >> 2);
            int col = n0 + wn * 64 + j * 8 + (lane & 3) * 2;
            float2 v0, v1;
            v0.x = acc[i][j][0] + bias[col];
            v0.y = acc[i][j][1] + bias[col + 1];
            v1.x = acc[i][j][2] + bias[col];
            v1.y = acc[i][j][3] + bias[col + 1];
            if (mode == 0) {
                int bb = row >> 11, tt = row & (TSEQ - 1);
                int which = col >> 10, h = (col >> 6) & (NHEAD - 1), d = col & (HDIM - 1);
                float* dst = (which == 0) ? g_Q : (which == 1) ? g_K : g_V;
                size_t base = ((size_t)(bb * NHEAD + h) * TSEQ);
                *reinterpret_cast<float2*>(&dst[(base + tt) * HDIM + d]) = v0;
                *reinterpret_cast<float2*>(&dst[(base + tt + 8) * HDIM + d]) = v1;
            } else {
                *reinterpret_cast<float2*>(&C[(size_t)row * DMODEL + col]) = v0;
                *reinterpret_cast<float2*>(&C[(size_t)(row + 8) * DMODEL + col]) = v1;
            }
        }
    }
}

// ===========================================================================
// Tensor-core flash attention, split-bf16, anti-causal mask (keep j >= i).
// CTA: 128 queries x 1 head, 8 warps x 16 rows. Key tiles of 64.
// Base-2 softmax: 0.125*log2(e) folded into Q; ex2.approx for exp.
// ===========================================================================
#define LKV 72                 // bf16 row stride (144B, conflict-free ldmatrix)
#define AQH 0
#define AQL (128*LKV*2)        // 18432
#define AKH (2*128*LKV*2)      // 36864
#define AKL (AKH + 64*LKV*2)   // +9216
#define AVH (AKL + 64*LKV*2)
#define AVL (AVH + 64*LKV*2)
#define ATT2_SMEM (AVL + 64*LKV*2)   // 73728

__global__ __launch_bounds__(256) void attn_mma_kernel()
{
    extern __shared__ char smem[];
    const uint32_t sb = smem_u32(smem);
    const int tid  = threadIdx.x;
    const int lane = tid & 31;
    const int warp = tid >> 5;       // 0..7, 16 query rows each
    const int q0 = blockIdx.x * 128;
    const int h  = blockIdx.y;
    const int b  = blockIdx.z;
    const size_t head_off = (size_t)(b * NHEAD + h) * TSEQ * HDIM;
    const float* Qg = g_Q + head_off;
    const float* Kg = g_K + head_off;
    const float* Vg = g_V + head_off;

    const float QSCALE = 0.18033688011112042f;   // 0.125 * log2(e)

    // ---- Stage Q (scaled, split) into smem ----
#pragma unroll
    for (int it = 0; it < 8; it++) {
        int idx = tid + it * 256;            // 2048 float4 slots
        int r = idx >> 4, c4 = (idx & 15) * 4;
        float4 v = *reinterpret_cast<const float4*>(&Qg[(size_t)(q0 + r) * HDIM + c4]);
        v.x *= QSCALE; v.y *= QSCALE; v.z *= QSCALE; v.w *= QSCALE;
        uint2 hi, lo;
        cvt_split(v, hi, lo);
        uint32_t eoff = (uint32_t)(r * LKV + c4) * 2u;
        *reinterpret_cast<uint2*>(smem + AQH + eoff) = hi;
        *reinterpret_cast<uint2*>(smem + AQL + eoff) = lo;
    }
    __syncthreads();

    // ---- Load Q fragments (A operand), 4 k-tiles of hd16, hi+lo ----
    uint32_t qh[4][4], ql[4][4];
    {
        const int aRow = warp * 16 + (lane & 15);
        const int aCol = (lane >> 4) * 8;
#pragma unroll
        for (int kt = 0; kt < 4; kt++) {
            uint32_t eo = (uint32_t)(aRow * LKV + kt * 16 + aCol) * 2u;
            ldsm_x4(qh[kt][0], qh[kt][1], qh[kt][2], qh[kt][3], sb + AQH + eo);
            ldsm_x4(ql[kt][0], ql[kt][1], ql[kt][2], ql[kt][3], sb + AQL + eo);
        }
    }

    float accO[8][4];
#pragma unroll
    for (int n = 0; n < 8; n++)
#pragma unroll
        for (int c = 0; c < 4; c++) accO[n][c] = 0.f;
    float mrow[2] = {-1e30f, -1e30f};
    float lrow[2] = {0.f, 0.f};

    for (int j0 = q0; j0 < TSEQ; j0 += 64) {
        // ---- Load K,V tile (64x64) split into smem ----
        __syncthreads();
#pragma unroll
        for (int it = 0; it < 4; it++) {
            int idx = tid + it * 256;        // 1024 slots
            int r = idx >> 4, c4 = (idx & 15) * 4;
            float4 kv = *reinterpret_cast<const float4*>(&Kg[(size_t)(j0 + r) * HDIM + c4]);
            float4 vv = *reinterpret_cast<const float4*>(&Vg[(size_t)(j0 + r) * HDIM + c4]);
            uint2 hi, lo;
            uint32_t eoff = (uint32_t)(r * LKV + c4) * 2u;
            cvt_split(kv, hi, lo);
            *reinterpret_cast<uint2*>(smem + AKH + eoff) = hi;
            *reinterpret_cast<uint2*>(smem + AKL + eoff) = lo;
            cvt_split(vv, hi, lo);
            *reinterpret_cast<uint2*>(smem + AVH + eoff) = hi;
            *reinterpret_cast<uint2*>(smem + AVL + eoff) = lo;
        }
        __syncthreads();

        // ---- S = Q*K^T (split, 3 products) ----
        float accS[8][4];
#pragma unroll
        for (int n = 0; n < 8; n++)
#pragma unroll
            for (int c = 0; c < 4; c++) accS[n][c] = 0.f;

        const int kRow = ((lane >> 4) * 8) + (lane & 7);
        const int kCol = ((lane >> 3) & 1) * 8;
#pragma unroll
        for (int kt = 0; kt < 4; kt++) {
#pragma unroll
            for (int j2 = 0; j2 < 4; j2++) {
                uint32_t eo = (uint32_t)((j2 * 16 + kRow) * LKV + kt * 16 + kCol) * 2u;
                uint32_t kh0, kh1, kh2, kh3, kl0, kl1, kl2, kl3;
                ldsm_x4(kh0, kh1, kh2, kh3, sb + AKH + eo);
                mma_bf16(accS[j2 * 2 + 0], qh[kt], kh0, kh1);
                mma_bf16(accS[j2 * 2 + 1], qh[kt], kh2, kh3);
                mma_bf16(accS[j2 * 2 + 0], ql[kt], kh0, kh1);
                mma_bf16(accS[j2 * 2 + 1], ql[kt], kh2, kh3);
                ldsm_x4(kl0, kl1, kl2, kl3, sb + AKL + eo);
                mma_bf16(accS[j2 * 2 + 0], qh[kt], kl0, kl1);
                mma_bf16(accS[j2 * 2 + 1], qh[kt], kl2, kl3);
            }
        }

        // ---- Mask (diag tiles only): keep key >= query ----
        if (j0 - q0 < 128) {
            int rq = q0 + warp * 16 + (lane >> 2);
#pragma unroll
            for (int nt = 0; nt < 8; nt++) {
                int cb = j0 + nt * 8 + 2 * (lane & 3);
                if (cb     < rq)     accS[nt][0] = -1e30f;
                if (cb + 1 < rq)     accS[nt][1] = -1e30f;
                if (cb     < rq + 8) accS[nt][2] = -1e30f;
                if (cb + 1 < rq + 8) accS[nt][3] = -1e30f;
            }
        }

        // ---- Online softmax (base-2 domain) ----
#pragma unroll
        for (int r = 0; r < 2; r++) {
            float tm = -1e30f;
#pragma unroll
            for (int nt = 0; nt < 8; nt++) {
                tm = fmaxf(tm, fmaxf(accS[nt][r * 2], accS[nt][r * 2 + 1]));
            }
            tm = fmaxf(tm, __shfl_xor_sync(0xffffffffu, tm, 1));
            tm = fmaxf(tm, __shfl_xor_sync(0xffffffffu, tm, 2));
            float mnew = fmaxf(mrow[r], tm);
            float alpha = ex2f(mrow[r] - mnew);
            mrow[r] = mnew;
            float rs = 0.f;
#pragma unroll
            for (int nt = 0; nt < 8; nt++) {
                float p0 = ex2f(accS[nt][r * 2]     - mnew);
                float p1 = ex2f(accS[nt][r * 2 + 1] - mnew);
                accS[nt][r * 2]     = p0;
                accS[nt][r * 2 + 1] = p1;
                rs += p0 + p1;
            }
            rs += __shfl_xor_sync(0xffffffffu, rs, 1);
            rs += __shfl_xor_sync(0xffffffffu, rs, 2);
            lrow[r] = lrow[r] * alpha + rs;
#pragma unroll
            for (int nt = 0; nt < 8; nt++) {
                accO[nt][r * 2]     *= alpha;
                accO[nt][r * 2 + 1] *= alpha;
            }
        }

        // ---- O += P*V (split, 3 products) ----
        const int vRow = lane & 15;
        const int vCol = (lane >> 4) * 8;
#pragma unroll
        for (int kt = 0; kt < 4; kt++) {
            // P fragments from S accumulators (C-frag -> A-frag identity)
            uint32_t pah[4], pal[4];
            {
                float s00 = accS[2 * kt][0],     s01 = accS[2 * kt][1];
                float s02 = accS[2 * kt][2],     s03 = accS[2 * kt][3];
                float s10 = accS[2 * kt + 1][0], s11 = accS[2 * kt + 1][1];
                float s12 = accS[2 * kt + 1][2], s13 = accS[2 * kt + 1][3];
                pah[0] = pack_bf16_hi(s00, s01);
                pah[1] = pack_bf16_hi(s02, s03);
                pah[2] = pack_bf16_hi(s10, s11);
                pah[3] = pack_bf16_hi(s12, s13);
                __nv_bfloat162* hp;
                hp = reinterpret_cast<__nv_bfloat162*>(&pah[0]);
                pal[0] = pack_bf16_hi(s00 - __bfloat162float(hp->x),
                                      s01 - __bfloat162float(hp->y));
                hp = reinterpret_cast<__nv_bfloat162*>(&pah[1]);
                pal[1] = pack_bf16_hi(s02 - __bfloat162float(hp->x),
                                      s03 - __bfloat162float(hp->y));
                hp = reinterpret_cast<__nv_bfloat162*>(&pah[2]);
                pal[2] = pack_bf16_hi(s10 - __bfloat162float(hp->x),
                                      s11 - __bfloat162float(hp->y));
                hp = reinterpret_cast<__nv_bfloat162*>(&pah[3]);
                pal[3] = pack_bf16_hi(s12 - __bfloat162float(hp->x),
                                      s13 - __bfloat162float(hp->y));
            }
#pragma unroll
            for (int n2 = 0; n2 < 4; n2++) {
                uint32_t eo = (uint32_t)((kt * 16 + vRow) * LKV + n2 * 16 + vCol) * 2u;
                uint32_t vh0, vh1, vh2, vh3, vl0, vl1, vl2, vl3;
                ldsm_x4_t(vh0, vh1, vh2, vh3, sb + AVH + eo);
                mma_bf16(accO[n2 * 2 + 0], pah, vh0, vh1);
                mma_bf16(accO[n2 * 2 + 1], pah, vh2, vh3);
                mma_bf16(accO[n2 * 2 + 0], pal, vh0, vh1);
                mma_bf16(accO[n2 * 2 + 1], pal, vh2, vh3);
                ldsm_x4_t(vl0, vl1, vl2, vl3, sb + AVL + eo);
                mma_bf16(accO[n2 * 2 + 0], pah, vl0, vl1);
                mma_bf16(accO[n2 * 2 + 1], pah, vl2, vl3);
            }
        }
    }

    // ---- Normalize and write to g_ATT [b*T + t][h*64 + hd] ----
    float inv0 = 1.0f / lrow[0];
    float inv1 = 1.0f / lrow[1];
    int t0 = q0 + warp * 16 + (lane >> 2);
    int t1 = t0 + 8;
#pragma unroll
    for (int nt = 0; nt < 8; nt++) {
        int hd = nt * 8 + 2 * (lane & 3);
        float2 v0, v1;
        v0.x = accO[nt][0] * inv0; v0.y = accO[nt][1] * inv0;
        v1.x = accO[nt][2] * inv1; v1.y = accO[nt][3] * inv1;
        *reinterpret_cast<float2*>(
            &g_ATT[((size_t)b * TSEQ + t0) * INNER + h * HDIM + hd]) = v0;
        *reinterpret_cast<float2*>(
            &g_ATT[((size_t)b * TSEQ + t1) * INNER + h * HDIM + hd]) = v1;
    }
}

// ===========================================================================
extern "C" void kernel_launch(void* const* d_in, const int* in_sizes, int n_in,
                              void* d_out, int out_size)
{
    const float* x     = (const float*)d_in[0];
    const float* qkv_w = (const float*)d_in[1];
    const float* qkv_b = (const float*)d_in[2];
    const float* out_w = (const float*)d_in[3];
    const float* out_b = (const float*)d_in[4];
    float* out = (float*)d_out;

    static int configured = 0;
    if (!configured) {
        cudaFuncSetAttribute(gemm_mma_kernel,
                             cudaFuncAttributeMaxDynamicSharedMemorySize, GEMM_SMEM);
        cudaFuncSetAttribute(attn_mma_kernel,
                             cudaFuncAttributeMaxDynamicSharedMemorySize, ATT2_SMEM);
        configured = 1;
    }

    dim3 g1(E3 / 128, MROWS / 128);
    gemm_mma_kernel<<<g1, 256, GEMM_SMEM>>>(x, qkv_w, qkv_b, nullptr, 0);

    dim3 g2(TSEQ / 128, NHEAD, BSZ);
    attn_mma_kernel<<<g2, 256, ATT2_SMEM>>>();

    dim3 g3(INNER / 128, MROWS / 128);
    gemm_mma_kernel<<<g3, 256, GEMM_SMEM>>>(nullptr, out_w, out_b, out, 1);
}